// round 1
// baseline (speedup 1.0000x reference)
#include <cuda_runtime.h>
#include <math.h>

#define DIMC 768
#define NHEADS 12
#define HD 64
#define HIDDENC 3072
#define SEQ 2048
#define BATCH 2
#define ROWS (BATCH * SEQ)   // 4096

// ---------------- scratch (device globals: no allocation allowed) ----------------
__device__ float g_h1[ROWS * DIMC];          // ln1 output
__device__ float g_qkv[ROWS * 3 * DIMC];     // qkv projection
__device__ float g_attn[ROWS * DIMC];        // attention output
__device__ float g_h2[ROWS * DIMC];          // ln2 output
__device__ float g_fc1[ROWS * HIDDENC];      // fc1+gelu output

// ---------------- LayerNorm: one block per row ----------------
__global__ void ln_kernel(const float* __restrict__ x,
                          const float* __restrict__ g,
                          const float* __restrict__ b,
                          float* __restrict__ out) {
    int row = blockIdx.x;
    const float* xr = x + (size_t)row * DIMC;
    float s = 0.f, s2 = 0.f;
    for (int i = threadIdx.x; i < DIMC; i += 256) {
        float v = xr[i];
        s += v; s2 += v * v;
    }
    #pragma unroll
    for (int o = 16; o; o >>= 1) {
        s  += __shfl_xor_sync(0xffffffffu, s,  o);
        s2 += __shfl_xor_sync(0xffffffffu, s2, o);
    }
    __shared__ float sm[8], sq[8];
    __shared__ float mu_s, rs_s;
    int w = threadIdx.x >> 5, l = threadIdx.x & 31;
    if (l == 0) { sm[w] = s; sq[w] = s2; }
    __syncthreads();
    if (threadIdx.x == 0) {
        float S = 0.f, S2 = 0.f;
        #pragma unroll
        for (int i = 0; i < 8; i++) { S += sm[i]; S2 += sq[i]; }
        float mu = S / DIMC;
        float var = S2 / DIMC - mu * mu;
        mu_s = mu;
        rs_s = rsqrtf(var + 1e-5f);
    }
    __syncthreads();
    float mu = mu_s, rs = rs_s;
    float* orow = out + (size_t)row * DIMC;
    for (int i = threadIdx.x; i < DIMC; i += 256)
        orow[i] = (xr[i] - mu) * rs * g[i] + b[i];
}

// ---------------- SGEMM 128x128x8, 256 threads, 8x8 micro-tile ----------------
// EPI: 0 = C = A@B + bias
//      1 = C = A@B + bias + res
//      2 = C = gelu(A@B + bias)   (exact, erf-based)
// All dims assumed divisible: M%128==0, N%128==0, K%8==0 (true for this problem).
template <int EPI>
__global__ __launch_bounds__(256, 2) void sgemm128(
    const float* __restrict__ A, const float* __restrict__ B,
    const float* __restrict__ bias, const float* __restrict__ res,
    float* __restrict__ C, int M, int N, int K) {
    __shared__ float As[8][132];
    __shared__ float Bs[8][132];
    int tid = threadIdx.x;
    int tx = tid & 15, ty = tid >> 4;
    int m0 = blockIdx.y * 128, n0 = blockIdx.x * 128;

    float acc[8][8] = {};

    int ar = tid >> 1;            // 0..127
    int akq = (tid & 1) * 4;      // 0 or 4
    int bk = tid >> 5;            // 0..7
    int bn = (tid & 31) * 4;      // 0..124

    const float* Ap = A + (size_t)(m0 + ar) * K + akq;
    const float* Bp = B + (size_t)bk * N + n0 + bn;

    for (int k0 = 0; k0 < K; k0 += 8) {
        float4 av = *(const float4*)(Ap + k0);
        float4 bv = *(const float4*)(Bp + (size_t)k0 * N);
        As[akq + 0][ar] = av.x;
        As[akq + 1][ar] = av.y;
        As[akq + 2][ar] = av.z;
        As[akq + 3][ar] = av.w;
        *(float4*)&Bs[bk][bn] = bv;
        __syncthreads();
        #pragma unroll
        for (int k = 0; k < 8; k++) {
            float4 a0 = *(float4*)&As[k][4 * ty];
            float4 a1 = *(float4*)&As[k][64 + 4 * ty];
            float4 b0 = *(float4*)&Bs[k][4 * tx];
            float4 b1 = *(float4*)&Bs[k][64 + 4 * tx];
            float a[8] = {a0.x, a0.y, a0.z, a0.w, a1.x, a1.y, a1.z, a1.w};
            float b[8] = {b0.x, b0.y, b0.z, b0.w, b1.x, b1.y, b1.z, b1.w};
            #pragma unroll
            for (int i = 0; i < 8; i++)
                #pragma unroll
                for (int j = 0; j < 8; j++)
                    acc[i][j] += a[i] * b[j];
        }
        __syncthreads();
    }

    #pragma unroll
    for (int i = 0; i < 8; i++) {
        int row = m0 + ((i < 4) ? (4 * ty + i) : (64 + 4 * ty + i - 4));
        #pragma unroll
        for (int j = 0; j < 8; j++) {
            int col = n0 + ((j < 4) ? (4 * tx + j) : (64 + 4 * tx + j - 4));
            float v = acc[i][j] + bias[col];
            if (EPI == 1) v += res[(size_t)row * N + col];
            if (EPI == 2) v = 0.5f * v * (1.0f + erff(v * 0.70710678118654752f));
            C[(size_t)row * N + col] = v;
        }
    }
}

// ---------------- Fused masked flash attention ----------------
// grid (SEQ/64, NHEADS, BATCH), block 256 (ty=tid/16 owns rows 4ty..4ty+3,
// tx owns cols/dims 4tx..4tx+3). Online softmax; mask folded per derivation:
//   out = sum_j e_ij * m_ij * V_j / (P_i + 1e-8 * S_i),
//   e = exp(s - rowmax), P = sum e*m, S = sum e, m = max(sigmoid(-bar*diff), 1e-6)
__global__ __launch_bounds__(256, 2) void attn_kernel(
    const float* __restrict__ qkv, const float* __restrict__ elev,
    const float* __restrict__ barrier_p, float* __restrict__ out) {
    extern __shared__ float smem[];
    float* Qt = smem;              // [64 d][68]  Qt[d][r]
    float* Kt = Qt + 64 * 68;      // [64 d][68]  Kt[d][c]
    float* Vs = Kt + 64 * 68;      // [64 j][68]  Vs[j][d]
    float* Pt = Vs + 64 * 68;      // [64 j][68]  Pt[j][r]
    __shared__ float eq_s[64], ek_s[64];

    int tid = threadIdx.x, tx = tid & 15, ty = tid >> 4;
    int q0 = blockIdx.x * 64;
    int h = blockIdx.y;
    int b = blockIdx.z;
    const float bar = barrier_p[0];
    const size_t base = (size_t)b * SEQ * (3 * DIMC);
    const int hoff = h * HD;

    // Load Q tile transposed
    for (int it = tid; it < 1024; it += 256) {
        int r = it >> 4, d4 = (it & 15) * 4;
        float4 v = *(const float4*)(qkv + base + (size_t)(q0 + r) * (3 * DIMC) + hoff + d4);
        Qt[(d4 + 0) * 68 + r] = v.x;
        Qt[(d4 + 1) * 68 + r] = v.y;
        Qt[(d4 + 2) * 68 + r] = v.z;
        Qt[(d4 + 3) * 68 + r] = v.w;
    }
    if (tid < 64) eq_s[tid] = elev[b * SEQ + q0 + tid];

    float m[4]    = {-INFINITY, -INFINITY, -INFINITY, -INFINITY};
    float Psum[4] = {0.f, 0.f, 0.f, 0.f};
    float Ssum[4] = {0.f, 0.f, 0.f, 0.f};
    float acc[4][4] = {};

    for (int j0 = 0; j0 < SEQ; j0 += 64) {
        __syncthreads();  // protect Kt/Vs/Pt from previous iteration's readers
        for (int it = tid; it < 1024; it += 256) {
            int r = it >> 4, d4 = (it & 15) * 4;
            const float* kp = qkv + base + (size_t)(j0 + r) * (3 * DIMC) + DIMC + hoff + d4;
            float4 kv = *(const float4*)kp;
            Kt[(d4 + 0) * 68 + r] = kv.x;
            Kt[(d4 + 1) * 68 + r] = kv.y;
            Kt[(d4 + 2) * 68 + r] = kv.z;
            Kt[(d4 + 3) * 68 + r] = kv.w;
            float4 vv = *(const float4*)(kp + DIMC);  // V is 768 floats after K
            *(float4*)&Vs[r * 68 + d4] = vv;
        }
        if (tid < 64) ek_s[tid] = elev[b * SEQ + j0 + tid];
        __syncthreads();

        // S = Q @ K^T  (4x4 micro-tile)
        float s[4][4] = {};
        #pragma unroll 8
        for (int k = 0; k < 64; k++) {
            float4 a  = *(float4*)&Qt[k * 68 + 4 * ty];
            float4 bv = *(float4*)&Kt[k * 68 + 4 * tx];
            float aa[4] = {a.x, a.y, a.z, a.w};
            float bb[4] = {bv.x, bv.y, bv.z, bv.w};
            #pragma unroll
            for (int i = 0; i < 4; i++)
                #pragma unroll
                for (int j = 0; j < 4; j++)
                    s[i][j] += aa[i] * bb[j];
        }
        #pragma unroll
        for (int i = 0; i < 4; i++)
            #pragma unroll
            for (int j = 0; j < 4; j++)
                s[i][j] *= 0.125f;  // HEAD_DIM^-0.5

        float eqv[4], ekv[4];
        #pragma unroll
        for (int i = 0; i < 4; i++) eqv[i] = eq_s[4 * ty + i];
        #pragma unroll
        for (int j = 0; j < 4; j++) ekv[j] = ek_s[4 * tx + j];

        #pragma unroll
        for (int i = 0; i < 4; i++) {
            float mx = fmaxf(fmaxf(s[i][0], s[i][1]), fmaxf(s[i][2], s[i][3]));
            #pragma unroll
            for (int o = 8; o; o >>= 1) mx = fmaxf(mx, __shfl_xor_sync(0xffffffffu, mx, o));
            float mn = fmaxf(m[i], mx);
            float f = expf(m[i] - mn);
            m[i] = mn;
            float ps = 0.f, ss = 0.f, p[4];
            #pragma unroll
            for (int j = 0; j < 4; j++) {
                float e = expf(s[i][j] - mn);
                float msk = fmaxf(1.0f / (1.0f + expf(bar * (ekv[j] - eqv[i]))), 1e-6f);
                p[j] = e * msk;
                ps += p[j];
                ss += e;
            }
            #pragma unroll
            for (int o = 8; o; o >>= 1) {
                ps += __shfl_xor_sync(0xffffffffu, ps, o);
                ss += __shfl_xor_sync(0xffffffffu, ss, o);
            }
            Psum[i] = Psum[i] * f + ps;
            Ssum[i] = Ssum[i] * f + ss;
            #pragma unroll
            for (int j = 0; j < 4; j++) {
                acc[i][j] *= f;
                Pt[(4 * tx + j) * 68 + 4 * ty + i] = p[j];
            }
        }
        __syncthreads();

        // acc += P @ V
        #pragma unroll 8
        for (int k = 0; k < 64; k++) {
            float4 a  = *(float4*)&Pt[k * 68 + 4 * ty];
            float4 bv = *(float4*)&Vs[k * 68 + 4 * tx];
            float aa[4] = {a.x, a.y, a.z, a.w};
            float bb[4] = {bv.x, bv.y, bv.z, bv.w};
            #pragma unroll
            for (int i = 0; i < 4; i++)
                #pragma unroll
                for (int j = 0; j < 4; j++)
                    acc[i][j] += aa[i] * bb[j];
        }
    }

    #pragma unroll
    for (int i = 0; i < 4; i++) {
        float inv = 1.0f / (Psum[i] + 1e-8f * Ssum[i]);
        int row = b * SEQ + q0 + 4 * ty + i;
        #pragma unroll
        for (int j = 0; j < 4; j++)
            out[(size_t)row * DIMC + hoff + 4 * tx + j] = acc[i][j] * inv;
    }
}

// ---------------- launch ----------------
extern "C" void kernel_launch(void* const* d_in, const int* in_sizes, int n_in,
                              void* d_out, int out_size) {
    const float* x       = (const float*)d_in[0];
    const float* elev    = (const float*)d_in[1];
    const float* qkv_w   = (const float*)d_in[2];
    const float* qkv_b   = (const float*)d_in[3];
    const float* proj_w  = (const float*)d_in[4];
    const float* proj_b  = (const float*)d_in[5];
    const float* ln1_g   = (const float*)d_in[6];
    const float* ln1_b   = (const float*)d_in[7];
    const float* ln2_g   = (const float*)d_in[8];
    const float* ln2_b   = (const float*)d_in[9];
    const float* fc1_w   = (const float*)d_in[10];
    const float* fc1_b   = (const float*)d_in[11];
    const float* fc2_w   = (const float*)d_in[12];
    const float* fc2_b   = (const float*)d_in[13];
    const float* barrier = (const float*)d_in[14];
    float* out = (float*)d_out;

    float *h1, *qkvb, *attn, *h2, *fc1o;
    cudaGetSymbolAddress((void**)&h1,   g_h1);
    cudaGetSymbolAddress((void**)&qkvb, g_qkv);
    cudaGetSymbolAddress((void**)&attn, g_attn);
    cudaGetSymbolAddress((void**)&h2,   g_h2);
    cudaGetSymbolAddress((void**)&fc1o, g_fc1);

    const int ATTN_SMEM = 4 * 64 * 68 * sizeof(float);  // 69632 B
    cudaFuncSetAttribute(attn_kernel, cudaFuncAttributeMaxDynamicSharedMemorySize, ATTN_SMEM);

    // 1. LN1
    ln_kernel<<<ROWS, 256>>>(x, ln1_g, ln1_b, h1);
    // 2. QKV = h1 @ qkv_w + b   [4096,768]x[768,2304]
    sgemm128<0><<<dim3(3 * DIMC / 128, ROWS / 128), 256>>>(h1, qkv_w, qkv_b, nullptr, qkvb,
                                                           ROWS, 3 * DIMC, DIMC);
    // 3. masked attention
    attn_kernel<<<dim3(SEQ / 64, NHEADS, BATCH), 256, ATTN_SMEM>>>(qkvb, elev, barrier, attn);
    // 4. x2 = x + attn @ proj_w + b  -> d_out
    sgemm128<1><<<dim3(DIMC / 128, ROWS / 128), 256>>>(attn, proj_w, proj_b, x, out,
                                                       ROWS, DIMC, DIMC);
    // 5. LN2 on x2
    ln_kernel<<<ROWS, 256>>>(out, ln2_g, ln2_b, h2);
    // 6. fc1 + gelu
    sgemm128<2><<<dim3(HIDDENC / 128, ROWS / 128), 256>>>(h2, fc1_w, fc1_b, nullptr, fc1o,
                                                          ROWS, HIDDENC, DIMC);
    // 7. out = x2 + fc1o @ fc2_w + b   (residual read/write d_out: each element
    //    read+written by exactly one thread, no cross-thread hazard)
    sgemm128<1><<<dim3(DIMC / 128, ROWS / 128), 256>>>(fc1o, fc2_w, fc2_b, out, out,
                                                       ROWS, DIMC, HIDDENC);
}

// round 6
// speedup vs baseline: 1.3985x; 1.3985x over previous
#include <cuda_runtime.h>
#include <cuda_bf16.h>
#include <math.h>
#include <stdint.h>

#define DIMC 768
#define NHEADS 12
#define HD 64
#define HIDDENC 3072
#define SEQ 2048
#define BATCH 2
#define ROWS (BATCH * SEQ)   // 4096

// ---------------- scratch (device globals) ----------------
__device__ __nv_bfloat16 g_aH[ROWS * DIMC];
__device__ __nv_bfloat16 g_aL[ROWS * DIMC];
__device__ __nv_bfloat16 g_fH[ROWS * HIDDENC];
__device__ __nv_bfloat16 g_fL[ROWS * HIDDENC];
__device__ float         g_qkv[ROWS * 3 * DIMC];
__device__ __nv_bfloat16 g_wqkvH[3 * DIMC * DIMC], g_wqkvL[3 * DIMC * DIMC];
__device__ __nv_bfloat16 g_wprojH[DIMC * DIMC],    g_wprojL[DIMC * DIMC];
__device__ __nv_bfloat16 g_wfc1H[HIDDENC * DIMC],  g_wfc1L[HIDDENC * DIMC];
__device__ __nv_bfloat16 g_wfc2H[DIMC * HIDDENC],  g_wfc2L[DIMC * HIDDENC];

// ---------------- helpers ----------------
__device__ __forceinline__ uint32_t smem_u32(const void* p) {
    uint32_t a;
    asm("{ .reg .u64 t; cvta.to.shared.u64 t, %1; cvt.u32.u64 %0, t; }" : "=r"(a) : "l"(p));
    return a;
}
__device__ __forceinline__ void cpa16(uint32_t dst, const void* src) {
    asm volatile("cp.async.cg.shared.global [%0], [%1], 16;" :: "r"(dst), "l"(src));
}
#define CP_COMMIT() asm volatile("cp.async.commit_group;" ::: "memory")

#define LDSM4(r, a) \
    asm volatile("ldmatrix.sync.aligned.m8n8.x4.shared.b16 {%0,%1,%2,%3}, [%4];" \
        : "=r"((r)[0]), "=r"((r)[1]), "=r"((r)[2]), "=r"((r)[3]) : "r"(a))

#define MMA16816(d, a, b) \
    asm volatile("mma.sync.aligned.m16n8k16.row.col.f32.bf16.bf16.f32 " \
        "{%0,%1,%2,%3}, {%4,%5,%6,%7}, {%8,%9}, {%0,%1,%2,%3};" \
        : "+f"((d)[0]), "+f"((d)[1]), "+f"((d)[2]), "+f"((d)[3]) \
        : "r"((a)[0]), "r"((a)[1]), "r"((a)[2]), "r"((a)[3]), "r"((b)[0]), "r"((b)[1]))

__device__ __forceinline__ void split2(float v, __nv_bfloat16& h, __nv_bfloat16& l) {
    h = __float2bfloat16(v);
    l = __float2bfloat16(v - __bfloat162float(h));
}

// swizzled smem offset for a [128][32] bf16 tile packed as [64][128B] rows:
// logical (r 0..127, c 0..31 bf16). 16B-group swizzle, conflict-free for
// ldmatrix (8 consecutive r at fixed c-group cover 8 distinct 16B lanes).
__device__ __forceinline__ uint32_t swz(int r, int c) {
    int p = r >> 1;
    int sub = ((r & 1) << 2) + (c >> 3);
    return (uint32_t)(p * 128 + (((sub ^ (p & 7)) << 4)) + ((c & 7) << 1));
}

// ---------------- LayerNorm -> bf16 hi/lo split ----------------
__global__ void ln_split(const float* __restrict__ x,
                         const float* __restrict__ g,
                         const float* __restrict__ b,
                         __nv_bfloat16* __restrict__ oh,
                         __nv_bfloat16* __restrict__ ol) {
    int row = blockIdx.x;
    const float* xr = x + (size_t)row * DIMC;
    float s = 0.f, s2 = 0.f;
    for (int i = threadIdx.x; i < DIMC; i += 256) {
        float v = xr[i];
        s += v; s2 += v * v;
    }
    #pragma unroll
    for (int o = 16; o; o >>= 1) {
        s  += __shfl_xor_sync(0xffffffffu, s,  o);
        s2 += __shfl_xor_sync(0xffffffffu, s2, o);
    }
    __shared__ float sm[8], sq[8];
    __shared__ float mu_s, rs_s;
    int w = threadIdx.x >> 5, l = threadIdx.x & 31;
    if (l == 0) { sm[w] = s; sq[w] = s2; }
    __syncthreads();
    if (threadIdx.x == 0) {
        float S = 0.f, S2 = 0.f;
        #pragma unroll
        for (int i = 0; i < 8; i++) { S += sm[i]; S2 += sq[i]; }
        float mu = S / DIMC;
        float var = S2 / DIMC - mu * mu;
        mu_s = mu;
        rs_s = rsqrtf(var + 1e-5f);
    }
    __syncthreads();
    float mu = mu_s, rs = rs_s;
    for (int i = threadIdx.x; i < DIMC; i += 256) {
        float v = (xr[i] - mu) * rs * g[i] + b[i];
        __nv_bfloat16 h, lo;
        split2(v, h, lo);
        oh[(size_t)row * DIMC + i] = h;
        ol[(size_t)row * DIMC + i] = lo;
    }
}

// ---------------- weight transpose + split: w[K,N] fp32 -> [N,K] bf16 hi/lo ----------------
__global__ void wsplit_t(const float* __restrict__ w,
                         __nv_bfloat16* __restrict__ oh,
                         __nv_bfloat16* __restrict__ ol, int K, int N) {
    __shared__ float t[32][33];
    int n0 = blockIdx.x * 32, k0 = blockIdx.y * 32;
    for (int r = threadIdx.y; r < 32; r += 8)
        t[r][threadIdx.x] = w[(size_t)(k0 + r) * N + n0 + threadIdx.x];
    __syncthreads();
    for (int r = threadIdx.y; r < 32; r += 8) {
        float v = t[threadIdx.x][r];
        __nv_bfloat16 h, lo;
        split2(v, h, lo);
        size_t o = (size_t)(n0 + r) * K + k0 + threadIdx.x;
        oh[o] = h;
        ol[o] = lo;
    }
}

// ---------------- HMMA GEMM: C[M,N] = split(A)[M,K] @ split(B)[N,K]^T ----------------
// EPI 0: C = acc + bias                      (fp32)
// EPI 1: C = acc + bias + res                (fp32)
// EPI 2: gelu(acc + bias) -> bf16 hi/lo (Ch/Cl)
// 128x128 CTA tile, 8 warps (4 along M x 2 along N; warp tile 32x64), BK=32,
// double-buffered cp.async. Stage layout: Ah+0, Al+8K, Bh+16K, Bl+24K (32KB/stage).
#define STG 32768
template <int EPI>
__global__ __launch_bounds__(256) void gemm_mma(
    const __nv_bfloat16* __restrict__ Ah, const __nv_bfloat16* __restrict__ Al,
    const __nv_bfloat16* __restrict__ Bh, const __nv_bfloat16* __restrict__ Bl,
    const float* __restrict__ bias, const float* __restrict__ res,
    float* __restrict__ C, __nv_bfloat16* __restrict__ Ch, __nv_bfloat16* __restrict__ Cl,
    int M, int N, int K) {
    extern __shared__ char smem[];
    uint32_t sb = smem_u32(smem);
    int tid = threadIdx.x, lane = tid & 31, w = tid >> 5;
    int m0 = blockIdx.y * 128, n0 = blockIdx.x * 128;
    int wm = (w & 3) * 32, wn = (w >> 2) * 64;

    float acc[2][8][4] = {};
    const int nchunk = K >> 5;

    // per-thread load slots: row r = tid>>1, two 16B segs
    int lr = tid >> 1;
    int ls0 = (tid & 1) * 2;
    uint32_t loff[2];
    #pragma unroll
    for (int j = 0; j < 2; j++) loff[j] = swz(lr, (ls0 + j) * 8);
    const __nv_bfloat16* gA[2];
    const __nv_bfloat16* gB[2];

    // issue chunk 0
    {
        int k0 = 0;
        #pragma unroll
        for (int j = 0; j < 2; j++) {
            size_t ga = (size_t)(m0 + lr) * K + k0 + (ls0 + j) * 8;
            size_t gb = (size_t)(n0 + lr) * K + k0 + (ls0 + j) * 8;
            cpa16(sb + loff[j],         Ah + ga);
            cpa16(sb + 8192 + loff[j],  Al + ga);
            cpa16(sb + 16384 + loff[j], Bh + gb);
            cpa16(sb + 24576 + loff[j], Bl + gb);
        }
        CP_COMMIT();
    }

    // ldmatrix per-lane address components
    int rA = (lane & 15);                          // + wm + tm*16
    int cAh = ((lane >> 4) << 3);                  // + ks
    int rB = (lane & 7) + ((lane >> 4) << 3);      // + wn + tn4*16
    int cBh = (((lane >> 3) & 1) << 3);            // + ks

    const uint32_t aoff[3] = {0u, 0u, 8192u};          // Ah, Ah, Al
    const uint32_t boff[3] = {16384u, 24576u, 16384u}; // Bh, Bl, Bh

    for (int c = 0; c < nchunk; c++) {
        if (c + 1 < nchunk) {
            uint32_t st = sb + ((c + 1) & 1) * STG;
            int k0 = (c + 1) << 5;
            #pragma unroll
            for (int j = 0; j < 2; j++) {
                size_t ga = (size_t)(m0 + lr) * K + k0 + (ls0 + j) * 8;
                size_t gb = (size_t)(n0 + lr) * K + k0 + (ls0 + j) * 8;
                cpa16(st + loff[j],         Ah + ga);
                cpa16(st + 8192 + loff[j],  Al + ga);
                cpa16(st + 16384 + loff[j], Bh + gb);
                cpa16(st + 24576 + loff[j], Bl + gb);
            }
            CP_COMMIT();
            asm volatile("cp.async.wait_group 1;" ::: "memory");
        } else {
            asm volatile("cp.async.wait_group 0;" ::: "memory");
        }
        __syncthreads();

        uint32_t stg = sb + (c & 1) * STG;
        #pragma unroll
        for (int term = 0; term < 3; term++) {
            uint32_t Ab = stg + aoff[term];
            uint32_t Bb = stg + boff[term];
            #pragma unroll
            for (int ks = 0; ks < 32; ks += 16) {
                uint32_t afr[2][4];
                #pragma unroll
                for (int tm = 0; tm < 2; tm++)
                    LDSM4(afr[tm], Ab + swz(wm + tm * 16 + rA, ks + cAh));
                uint32_t bfr[8][2];
                #pragma unroll
                for (int t4 = 0; t4 < 4; t4++) {
                    uint32_t q[4];
                    LDSM4(q, Bb + swz(wn + t4 * 16 + rB, ks + cBh));
                    bfr[2 * t4][0] = q[0]; bfr[2 * t4][1] = q[1];
                    bfr[2 * t4 + 1][0] = q[2]; bfr[2 * t4 + 1][1] = q[3];
                }
                #pragma unroll
                for (int tm = 0; tm < 2; tm++)
                    #pragma unroll
                    for (int tn = 0; tn < 8; tn++)
                        MMA16816(acc[tm][tn], afr[tm], bfr[tn]);
            }
        }
        __syncthreads();
    }

    // epilogue: each thread owns (row, col..col+1) and (row+8, ...)
    #pragma unroll
    for (int tm = 0; tm < 2; tm++) {
        #pragma unroll
        for (int tn = 0; tn < 8; tn++) {
            int row = m0 + wm + tm * 16 + (lane >> 2);
            int col = n0 + wn + tn * 8 + ((lane & 3) << 1);
            float b0 = bias[col], b1 = bias[col + 1];
            float* a = acc[tm][tn];
            #pragma unroll
            for (int hrow = 0; hrow < 2; hrow++) {
                int rr = row + hrow * 8;
                float v0 = a[2 * hrow + 0] + b0;
                float v1 = a[2 * hrow + 1] + b1;
                size_t o = (size_t)rr * N + col;
                if (EPI == 0) {
                    float2 v = {v0, v1};
                    *(float2*)(C + o) = v;
                } else if (EPI == 1) {
                    float2 rv = *(const float2*)(res + o);
                    float2 v = {v0 + rv.x, v1 + rv.y};
                    *(float2*)(C + o) = v;
                } else {
                    float g0 = 0.5f * v0 * (1.0f + erff(v0 * 0.70710678118654752f));
                    float g1 = 0.5f * v1 * (1.0f + erff(v1 * 0.70710678118654752f));
                    __nv_bfloat16 h0, l0, h1, l1;
                    split2(g0, h0, l0);
                    split2(g1, h1, l1);
                    __nv_bfloat162 hh; hh.x = h0; hh.y = h1;
                    __nv_bfloat162 ll; ll.x = l0; ll.y = l1;
                    *(__nv_bfloat162*)(Ch + o) = hh;
                    *(__nv_bfloat162*)(Cl + o) = ll;
                }
            }
        }
    }
}

// ---------------- fused masked flash attention (SIMT), split bf16 output ----------------
__global__ __launch_bounds__(256, 2) void attn_kernel(
    const float* __restrict__ qkv, const float* __restrict__ elev,
    const float* __restrict__ barrier_p,
    __nv_bfloat16* __restrict__ outH, __nv_bfloat16* __restrict__ outL) {
    extern __shared__ float smemf[];
    float* Qt = smemf;
    float* Kt = Qt + 64 * 68;
    float* Vs = Kt + 64 * 68;
    float* Pt = Vs + 64 * 68;
    __shared__ float eq_s[64], ek_s[64];

    int tid = threadIdx.x, tx = tid & 15, ty = tid >> 4;
    int q0 = blockIdx.x * 64;
    int h = blockIdx.y;
    int b = blockIdx.z;
    const float bar = barrier_p[0];
    const size_t base = (size_t)b * SEQ * (3 * DIMC);
    const int hoff = h * HD;

    for (int it = tid; it < 1024; it += 256) {
        int r = it >> 4, d4 = (it & 15) * 4;
        float4 v = *(const float4*)(qkv + base + (size_t)(q0 + r) * (3 * DIMC) + hoff + d4);
        Qt[(d4 + 0) * 68 + r] = v.x;
        Qt[(d4 + 1) * 68 + r] = v.y;
        Qt[(d4 + 2) * 68 + r] = v.z;
        Qt[(d4 + 3) * 68 + r] = v.w;
    }
    if (tid < 64) eq_s[tid] = elev[b * SEQ + q0 + tid];

    float m[4]    = {-INFINITY, -INFINITY, -INFINITY, -INFINITY};
    float Psum[4] = {0.f, 0.f, 0.f, 0.f};
    float Ssum[4] = {0.f, 0.f, 0.f, 0.f};
    float acc[4][4] = {};

    for (int j0 = 0; j0 < SEQ; j0 += 64) {
        __syncthreads();
        for (int it = tid; it < 1024; it += 256) {
            int r = it >> 4, d4 = (it & 15) * 4;
            const float* kp = qkv + base + (size_t)(j0 + r) * (3 * DIMC) + DIMC + hoff + d4;
            float4 kv = *(const float4*)kp;
            Kt[(d4 + 0) * 68 + r] = kv.x;
            Kt[(d4 + 1) * 68 + r] = kv.y;
            Kt[(d4 + 2) * 68 + r] = kv.z;
            Kt[(d4 + 3) * 68 + r] = kv.w;
            float4 vv = *(const float4*)(kp + DIMC);
            *(float4*)&Vs[r * 68 + d4] = vv;
        }
        if (tid < 64) ek_s[tid] = elev[b * SEQ + j0 + tid];
        __syncthreads();

        float s[4][4] = {};
        #pragma unroll 8
        for (int k = 0; k < 64; k++) {
            float4 a  = *(float4*)&Qt[k * 68 + 4 * ty];
            float4 bv = *(float4*)&Kt[k * 68 + 4 * tx];
            float aa[4] = {a.x, a.y, a.z, a.w};
            float bb[4] = {bv.x, bv.y, bv.z, bv.w};
            #pragma unroll
            for (int i = 0; i < 4; i++)
                #pragma unroll
                for (int j = 0; j < 4; j++)
                    s[i][j] += aa[i] * bb[j];
        }
        #pragma unroll
        for (int i = 0; i < 4; i++)
            #pragma unroll
            for (int j = 0; j < 4; j++)
                s[i][j] *= 0.125f;

        float eqv[4], ekv[4];
        #pragma unroll
        for (int i = 0; i < 4; i++) eqv[i] = eq_s[4 * ty + i];
        #pragma unroll
        for (int j = 0; j < 4; j++) ekv[j] = ek_s[4 * tx + j];

        #pragma unroll
        for (int i = 0; i < 4; i++) {
            float mx = fmaxf(fmaxf(s[i][0], s[i][1]), fmaxf(s[i][2], s[i][3]));
            #pragma unroll
            for (int o = 8; o; o >>= 1) mx = fmaxf(mx, __shfl_xor_sync(0xffffffffu, mx, o));
            float mn = fmaxf(m[i], mx);
            float f = expf(m[i] - mn);
            m[i] = mn;
            float ps = 0.f, ss = 0.f, p[4];
            #pragma unroll
            for (int j = 0; j < 4; j++) {
                float e = expf(s[i][j] - mn);
                float msk = fmaxf(1.0f / (1.0f + expf(bar * (ekv[j] - eqv[i]))), 1e-6f);
                p[j] = e * msk;
                ps += p[j];
                ss += e;
            }
            #pragma unroll
            for (int o = 8; o; o >>= 1) {
                ps += __shfl_xor_sync(0xffffffffu, ps, o);
                ss += __shfl_xor_sync(0xffffffffu, ss, o);
            }
            Psum[i] = Psum[i] * f + ps;
            Ssum[i] = Ssum[i] * f + ss;
            #pragma unroll
            for (int j = 0; j < 4; j++) {
                acc[i][j] *= f;
                Pt[(4 * tx + j) * 68 + 4 * ty + i] = p[j];
            }
        }
        __syncthreads();

        #pragma unroll 8
        for (int k = 0; k < 64; k++) {
            float4 a  = *(float4*)&Pt[k * 68 + 4 * ty];
            float4 bv = *(float4*)&Vs[k * 68 + 4 * tx];
            float aa[4] = {a.x, a.y, a.z, a.w};
            float bb[4] = {bv.x, bv.y, bv.z, bv.w};
            #pragma unroll
            for (int i = 0; i < 4; i++)
                #pragma unroll
                for (int j = 0; j < 4; j++)
                    acc[i][j] += aa[i] * bb[j];
        }
    }

    #pragma unroll
    for (int i = 0; i < 4; i++) {
        float inv = 1.0f / (Psum[i] + 1e-8f * Ssum[i]);
        int row = b * SEQ + q0 + 4 * ty + i;
        #pragma unroll
        for (int j = 0; j < 4; j++) {
            float v = acc[i][j] * inv;
            __nv_bfloat16 hh, ll;
            split2(v, hh, ll);
            size_t o = (size_t)row * DIMC + hoff + 4 * tx + j;
            outH[o] = hh;
            outL[o] = ll;
        }
    }
}

// ---------------- launch ----------------
extern "C" void kernel_launch(void* const* d_in, const int* in_sizes, int n_in,
                              void* d_out, int out_size) {
    const float* x       = (const float*)d_in[0];
    const float* elev    = (const float*)d_in[1];
    const float* qkv_w   = (const float*)d_in[2];
    const float* qkv_b   = (const float*)d_in[3];
    const float* proj_w  = (const float*)d_in[4];
    const float* proj_b  = (const float*)d_in[5];
    const float* ln1_g   = (const float*)d_in[6];
    const float* ln1_b   = (const float*)d_in[7];
    const float* ln2_g   = (const float*)d_in[8];
    const float* ln2_b   = (const float*)d_in[9];
    const float* fc1_w   = (const float*)d_in[10];
    const float* fc1_b   = (const float*)d_in[11];
    const float* fc2_w   = (const float*)d_in[12];
    const float* fc2_b   = (const float*)d_in[13];
    const float* barrier = (const float*)d_in[14];
    float* out = (float*)d_out;

    __nv_bfloat16 *aH, *aL, *fH, *fL;
    __nv_bfloat16 *wqH, *wqL, *wpH, *wpL, *w1H, *w1L, *w2H, *w2L;
    float* qkvb;
    cudaGetSymbolAddress((void**)&aH, g_aH);     cudaGetSymbolAddress((void**)&aL, g_aL);
    cudaGetSymbolAddress((void**)&fH, g_fH);     cudaGetSymbolAddress((void**)&fL, g_fL);
    cudaGetSymbolAddress((void**)&qkvb, g_qkv);
    cudaGetSymbolAddress((void**)&wqH, g_wqkvH); cudaGetSymbolAddress((void**)&wqL, g_wqkvL);
    cudaGetSymbolAddress((void**)&wpH, g_wprojH);cudaGetSymbolAddress((void**)&wpL, g_wprojL);
    cudaGetSymbolAddress((void**)&w1H, g_wfc1H); cudaGetSymbolAddress((void**)&w1L, g_wfc1L);
    cudaGetSymbolAddress((void**)&w2H, g_wfc2H); cudaGetSymbolAddress((void**)&w2L, g_wfc2L);

    const int GEMM_SMEM = 2 * STG;   // 65536
    cudaFuncSetAttribute(gemm_mma<0>, cudaFuncAttributeMaxDynamicSharedMemorySize, GEMM_SMEM);
    cudaFuncSetAttribute(gemm_mma<1>, cudaFuncAttributeMaxDynamicSharedMemorySize, GEMM_SMEM);
    cudaFuncSetAttribute(gemm_mma<2>, cudaFuncAttributeMaxDynamicSharedMemorySize, GEMM_SMEM);
    const int ATTN_SMEM = 4 * 64 * 68 * sizeof(float);
    cudaFuncSetAttribute(attn_kernel, cudaFuncAttributeMaxDynamicSharedMemorySize, ATTN_SMEM);

    dim3 tb(32, 8);
    wsplit_t<<<dim3(3 * DIMC / 32, DIMC / 32), tb>>>(qkv_w, wqH, wqL, DIMC, 3 * DIMC);
    wsplit_t<<<dim3(DIMC / 32, DIMC / 32), tb>>>(proj_w, wpH, wpL, DIMC, DIMC);
    wsplit_t<<<dim3(HIDDENC / 32, DIMC / 32), tb>>>(fc1_w, w1H, w1L, DIMC, HIDDENC);
    wsplit_t<<<dim3(DIMC / 32, HIDDENC / 32), tb>>>(fc2_w, w2H, w2L, HIDDENC, DIMC);

    // 1. LN1 -> splits
    ln_split<<<ROWS, 256>>>(x, ln1_g, ln1_b, aH, aL);
    // 2. QKV = ln1 @ qkv_w + b
    gemm_mma<0><<<dim3(3 * DIMC / 128, ROWS / 128), 256, GEMM_SMEM>>>(
        aH, aL, wqH, wqL, qkv_b, nullptr, qkvb, nullptr, nullptr, ROWS, 3 * DIMC, DIMC);
    // 3. attention -> splits
    attn_kernel<<<dim3(SEQ / 64, NHEADS, BATCH), 256, ATTN_SMEM>>>(qkvb, elev, barrier, aH, aL);
    // 4. x2 = x + attn @ proj_w + b -> d_out
    gemm_mma<1><<<dim3(DIMC / 128, ROWS / 128), 256, GEMM_SMEM>>>(
        aH, aL, wpH, wpL, proj_b, x, out, nullptr, nullptr, ROWS, DIMC, DIMC);
    // 5. LN2 -> splits
    ln_split<<<ROWS, 256>>>(out, ln2_g, ln2_b, aH, aL);
    // 6. fc1 + gelu -> splits
    gemm_mma<2><<<dim3(HIDDENC / 128, ROWS / 128), 256, GEMM_SMEM>>>(
        aH, aL, w1H, w1L, fc1_b, nullptr, nullptr, fH, fL, ROWS, HIDDENC, DIMC);
    // 7. out = x2 + fc1 @ fc2_w + b
    gemm_mma<1><<<dim3(DIMC / 128, ROWS / 128), 256, GEMM_SMEM>>>(
        fH, fL, w2H, w2L, fc2_b, out, out, nullptr, nullptr, ROWS, DIMC, HIDDENC);
}

// round 7
// speedup vs baseline: 2.2114x; 1.5812x over previous
#include <cuda_runtime.h>
#include <cuda_bf16.h>
#include <math.h>
#include <stdint.h>

#define DIMC 768
#define NHEADS 12
#define HD 64
#define HIDDENC 3072
#define SEQ 2048
#define BATCH 2
#define ROWS (BATCH * SEQ)   // 4096

// ---------------- scratch (device globals) ----------------
__device__ __nv_bfloat16 g_aH[ROWS * DIMC];
__device__ __nv_bfloat16 g_aL[ROWS * DIMC];
__device__ __nv_bfloat16 g_fH[ROWS * HIDDENC];
__device__ __nv_bfloat16 g_fL[ROWS * HIDDENC];
__device__ float         g_qkv[ROWS * 3 * DIMC];
__device__ __nv_bfloat16 g_wqkvH[3 * DIMC * DIMC], g_wqkvL[3 * DIMC * DIMC];
__device__ __nv_bfloat16 g_wprojH[DIMC * DIMC],    g_wprojL[DIMC * DIMC];
__device__ __nv_bfloat16 g_wfc1H[HIDDENC * DIMC],  g_wfc1L[HIDDENC * DIMC];
__device__ __nv_bfloat16 g_wfc2H[DIMC * HIDDENC],  g_wfc2L[DIMC * HIDDENC];

// ---------------- helpers ----------------
__device__ __forceinline__ uint32_t smem_u32(const void* p) {
    uint32_t a;
    asm("{ .reg .u64 t; cvta.to.shared.u64 t, %1; cvt.u32.u64 %0, t; }" : "=r"(a) : "l"(p));
    return a;
}
__device__ __forceinline__ void cpa16(uint32_t dst, const void* src) {
    asm volatile("cp.async.cg.shared.global [%0], [%1], 16;" :: "r"(dst), "l"(src));
}
#define CP_COMMIT() asm volatile("cp.async.commit_group;" ::: "memory")

#define LDSM4(r, a) \
    asm volatile("ldmatrix.sync.aligned.m8n8.x4.shared.b16 {%0,%1,%2,%3}, [%4];" \
        : "=r"((r)[0]), "=r"((r)[1]), "=r"((r)[2]), "=r"((r)[3]) : "r"(a))
#define LDSM4T(r, a) \
    asm volatile("ldmatrix.sync.aligned.m8n8.x4.trans.shared.b16 {%0,%1,%2,%3}, [%4];" \
        : "=r"((r)[0]), "=r"((r)[1]), "=r"((r)[2]), "=r"((r)[3]) : "r"(a))

#define MMA16816(d, a, b) \
    asm volatile("mma.sync.aligned.m16n8k16.row.col.f32.bf16.bf16.f32 " \
        "{%0,%1,%2,%3}, {%4,%5,%6,%7}, {%8,%9}, {%0,%1,%2,%3};" \
        : "+f"((d)[0]), "+f"((d)[1]), "+f"((d)[2]), "+f"((d)[3]) \
        : "r"((a)[0]), "r"((a)[1]), "r"((a)[2]), "r"((a)[3]), "r"((b)[0]), "r"((b)[1]))

__device__ __forceinline__ void split2(float v, __nv_bfloat16& h, __nv_bfloat16& l) {
    h = __float2bfloat16(v);
    l = __float2bfloat16(v - __bfloat162float(h));
}
// pack (a,b) pair to bf16x2 hi word; lo split via out-param
__device__ __forceinline__ uint32_t packsplit(float a, float b, uint32_t& lo) {
    __nv_bfloat16 ah, al, bh, bl;
    split2(a, ah, al);
    split2(b, bh, bl);
    lo = (uint32_t)__bfloat16_as_ushort(al) | ((uint32_t)__bfloat16_as_ushort(bl) << 16);
    return (uint32_t)__bfloat16_as_ushort(ah) | ((uint32_t)__bfloat16_as_ushort(bh) << 16);
}

// gemm tile swizzle: [128][32] bf16 packed in 64 x 128B rows
__device__ __forceinline__ uint32_t swz(int r, int c) {
    int p = r >> 1;
    int sub = ((r & 1) << 2) + (c >> 3);
    return (uint32_t)(p * 128 + (((sub ^ (p & 7)) << 4)) + ((c & 7) << 1));
}
// attention tile swizzle: [.][64] bf16, 128B per row (byte offset)
__device__ __forceinline__ uint32_t asw(int r, int c) {
    return (uint32_t)(r * 128 + ((((c >> 3) ^ (r & 7)) << 4)) + ((c & 7) << 1));
}

// ---------------- LayerNorm -> bf16 hi/lo split ----------------
__global__ void ln_split(const float* __restrict__ x,
                         const float* __restrict__ g,
                         const float* __restrict__ b,
                         __nv_bfloat16* __restrict__ oh,
                         __nv_bfloat16* __restrict__ ol) {
    int row = blockIdx.x;
    const float* xr = x + (size_t)row * DIMC;
    float s = 0.f, s2 = 0.f;
    for (int i = threadIdx.x; i < DIMC; i += 256) {
        float v = xr[i];
        s += v; s2 += v * v;
    }
    #pragma unroll
    for (int o = 16; o; o >>= 1) {
        s  += __shfl_xor_sync(0xffffffffu, s,  o);
        s2 += __shfl_xor_sync(0xffffffffu, s2, o);
    }
    __shared__ float sm[8], sq[8];
    __shared__ float mu_s, rs_s;
    int w = threadIdx.x >> 5, l = threadIdx.x & 31;
    if (l == 0) { sm[w] = s; sq[w] = s2; }
    __syncthreads();
    if (threadIdx.x == 0) {
        float S = 0.f, S2 = 0.f;
        #pragma unroll
        for (int i = 0; i < 8; i++) { S += sm[i]; S2 += sq[i]; }
        float mu = S / DIMC;
        float var = S2 / DIMC - mu * mu;
        mu_s = mu;
        rs_s = rsqrtf(var + 1e-5f);
    }
    __syncthreads();
    float mu = mu_s, rs = rs_s;
    for (int i = threadIdx.x; i < DIMC; i += 256) {
        float v = (xr[i] - mu) * rs * g[i] + b[i];
        __nv_bfloat16 h, lo;
        split2(v, h, lo);
        oh[(size_t)row * DIMC + i] = h;
        ol[(size_t)row * DIMC + i] = lo;
    }
}

// ---------------- weight transpose + split: w[K,N] fp32 -> [N,K] bf16 hi/lo ----------------
__global__ void wsplit_t(const float* __restrict__ w,
                         __nv_bfloat16* __restrict__ oh,
                         __nv_bfloat16* __restrict__ ol, int K, int N) {
    __shared__ float t[32][33];
    int n0 = blockIdx.x * 32, k0 = blockIdx.y * 32;
    for (int r = threadIdx.y; r < 32; r += 8)
        t[r][threadIdx.x] = w[(size_t)(k0 + r) * N + n0 + threadIdx.x];
    __syncthreads();
    for (int r = threadIdx.y; r < 32; r += 8) {
        float v = t[threadIdx.x][r];
        __nv_bfloat16 h, lo;
        split2(v, h, lo);
        size_t o = (size_t)(n0 + r) * K + k0 + threadIdx.x;
        oh[o] = h;
        ol[o] = lo;
    }
}

// ---------------- HMMA GEMM (validated R6) ----------------
#define STG 32768
template <int EPI>
__global__ __launch_bounds__(256) void gemm_mma(
    const __nv_bfloat16* __restrict__ Ah, const __nv_bfloat16* __restrict__ Al,
    const __nv_bfloat16* __restrict__ Bh, const __nv_bfloat16* __restrict__ Bl,
    const float* __restrict__ bias, const float* __restrict__ res,
    float* __restrict__ C, __nv_bfloat16* __restrict__ Ch, __nv_bfloat16* __restrict__ Cl,
    int M, int N, int K) {
    extern __shared__ char smem[];
    uint32_t sb = smem_u32(smem);
    int tid = threadIdx.x, lane = tid & 31, w = tid >> 5;
    int m0 = blockIdx.y * 128, n0 = blockIdx.x * 128;
    int wm = (w & 3) * 32, wn = (w >> 2) * 64;

    float acc[2][8][4] = {};
    const int nchunk = K >> 5;

    int lr = tid >> 1;
    int ls0 = (tid & 1) * 2;
    uint32_t loff[2];
    #pragma unroll
    for (int j = 0; j < 2; j++) loff[j] = swz(lr, (ls0 + j) * 8);

    {
        int k0 = 0;
        #pragma unroll
        for (int j = 0; j < 2; j++) {
            size_t ga = (size_t)(m0 + lr) * K + k0 + (ls0 + j) * 8;
            size_t gb = (size_t)(n0 + lr) * K + k0 + (ls0 + j) * 8;
            cpa16(sb + loff[j],         Ah + ga);
            cpa16(sb + 8192 + loff[j],  Al + ga);
            cpa16(sb + 16384 + loff[j], Bh + gb);
            cpa16(sb + 24576 + loff[j], Bl + gb);
        }
        CP_COMMIT();
    }

    int rA = (lane & 15);
    int cAh = ((lane >> 4) << 3);
    int rB = (lane & 7) + ((lane >> 4) << 3);
    int cBh = (((lane >> 3) & 1) << 3);

    const uint32_t aoff[3] = {0u, 0u, 8192u};
    const uint32_t boff[3] = {16384u, 24576u, 16384u};

    for (int c = 0; c < nchunk; c++) {
        if (c + 1 < nchunk) {
            uint32_t st = sb + ((c + 1) & 1) * STG;
            int k0 = (c + 1) << 5;
            #pragma unroll
            for (int j = 0; j < 2; j++) {
                size_t ga = (size_t)(m0 + lr) * K + k0 + (ls0 + j) * 8;
                size_t gb = (size_t)(n0 + lr) * K + k0 + (ls0 + j) * 8;
                cpa16(st + loff[j],         Ah + ga);
                cpa16(st + 8192 + loff[j],  Al + ga);
                cpa16(st + 16384 + loff[j], Bh + gb);
                cpa16(st + 24576 + loff[j], Bl + gb);
            }
            CP_COMMIT();
            asm volatile("cp.async.wait_group 1;" ::: "memory");
        } else {
            asm volatile("cp.async.wait_group 0;" ::: "memory");
        }
        __syncthreads();

        uint32_t stg = sb + (c & 1) * STG;
        #pragma unroll
        for (int term = 0; term < 3; term++) {
            uint32_t Ab = stg + aoff[term];
            uint32_t Bb = stg + boff[term];
            #pragma unroll
            for (int ks = 0; ks < 32; ks += 16) {
                uint32_t afr[2][4];
                #pragma unroll
                for (int tm = 0; tm < 2; tm++)
                    LDSM4(afr[tm], Ab + swz(wm + tm * 16 + rA, ks + cAh));
                uint32_t bfr[8][2];
                #pragma unroll
                for (int t4 = 0; t4 < 4; t4++) {
                    uint32_t q[4];
                    LDSM4(q, Bb + swz(wn + t4 * 16 + rB, ks + cBh));
                    bfr[2 * t4][0] = q[0]; bfr[2 * t4][1] = q[1];
                    bfr[2 * t4 + 1][0] = q[2]; bfr[2 * t4 + 1][1] = q[3];
                }
                #pragma unroll
                for (int tm = 0; tm < 2; tm++)
                    #pragma unroll
                    for (int tn = 0; tn < 8; tn++)
                        MMA16816(acc[tm][tn], afr[tm], bfr[tn]);
            }
        }
        __syncthreads();
    }

    #pragma unroll
    for (int tm = 0; tm < 2; tm++) {
        #pragma unroll
        for (int tn = 0; tn < 8; tn++) {
            int row = m0 + wm + tm * 16 + (lane >> 2);
            int col = n0 + wn + tn * 8 + ((lane & 3) << 1);
            float b0 = bias[col], b1 = bias[col + 1];
            float* a = acc[tm][tn];
            #pragma unroll
            for (int hrow = 0; hrow < 2; hrow++) {
                int rr = row + hrow * 8;
                float v0 = a[2 * hrow + 0] + b0;
                float v1 = a[2 * hrow + 1] + b1;
                size_t o = (size_t)rr * N + col;
                if (EPI == 0) {
                    float2 v = {v0, v1};
                    *(float2*)(C + o) = v;
                } else if (EPI == 1) {
                    float2 rv = *(const float2*)(res + o);
                    float2 v = {v0 + rv.x, v1 + rv.y};
                    *(float2*)(C + o) = v;
                } else {
                    float g0 = 0.5f * v0 * (1.0f + erff(v0 * 0.70710678118654752f));
                    float g1 = 0.5f * v1 * (1.0f + erff(v1 * 0.70710678118654752f));
                    uint32_t lo;
                    uint32_t hi = packsplit(g0, g1, lo);
                    *(uint32_t*)(Ch + o) = hi;
                    *(uint32_t*)(Cl + o) = lo;
                }
            }
        }
    }
}

// ---------------- tensorized masked flash attention ----------------
// Block: 128 q-rows x 1 head. 8 warps x 16 rows. j-tiles of 64.
// smem: Qh 0 | Ql 16K | Kh 32K | Kl 40K | Vh 48K... (bytes below)
#define AQH 0
#define AQL 16384
#define AKH 32768
#define AKL 40960
#define AVH 49152
#define AVL 57344
#define ATTN_SM 65536
__global__ __launch_bounds__(256) void attn_mma(
    const float* __restrict__ qkv, const float* __restrict__ elev,
    const float* __restrict__ barrier_p,
    __nv_bfloat16* __restrict__ outH, __nv_bfloat16* __restrict__ outL) {
    extern __shared__ char smem[];
    uint32_t sb = smem_u32(smem);
    __shared__ float eq_s[128], ek_s[64];

    int tid = threadIdx.x, lane = tid & 31, w = tid >> 5;
    int q0 = blockIdx.x * 128;
    int h = blockIdx.y;
    int b = blockIdx.z;
    const float bar = barrier_p[0];
    const size_t base = (size_t)b * SEQ * (3 * DIMC);
    const int hoff = h * HD;
    const int wm = w * 16;

    // stage Q (scaled by 2^-3, exact) as bf16 hi/lo
    #pragma unroll
    for (int i = 0; i < 16; i++) {
        int row = wm + i;
        float2 qv = *(const float2*)(qkv + base + (size_t)(q0 + row) * (3 * DIMC) + hoff + 2 * lane);
        uint32_t lo;
        uint32_t hi = packsplit(qv.x * 0.125f, qv.y * 0.125f, lo);
        uint32_t o = asw(row, 2 * lane);
        *(uint32_t*)(smem + AQH + o) = hi;
        *(uint32_t*)(smem + AQL + o) = lo;
    }
    if (tid < 128) eq_s[tid] = elev[b * SEQ + q0 + tid];

    // per-thread row stats (rows lane>>2 and +8 within warp tile)
    float m0 = -1e30f, m1 = -1e30f;
    float P0 = 0.f, P1 = 0.f, S0 = 0.f, S1 = 0.f;
    float oacc[8][4] = {};

    const int rA = lane & 15;
    const int cA = (lane >> 4) << 3;
    const int rB = (lane & 7) + ((lane >> 4) << 3);
    const int cB = ((lane >> 3) & 1) << 3;
    // V trans-load lane addr components
    const int vj = (((lane >> 3) & 1) << 3) + (lane & 7);
    const int vd = (lane >> 4) << 3;

    for (int j0 = 0; j0 < SEQ; j0 += 64) {
        __syncthreads();
        // stage K, V tiles
        #pragma unroll
        for (int i = 0; i < 8; i++) {
            int jr = w * 8 + i;
            const float* kp = qkv + base + (size_t)(j0 + jr) * (3 * DIMC) + DIMC + hoff + 2 * lane;
            float2 kv = *(const float2*)kp;
            float2 vv = *(const float2*)(kp + DIMC);
            uint32_t o = asw(jr, 2 * lane);
            uint32_t lo;
            uint32_t hi = packsplit(kv.x, kv.y, lo);
            *(uint32_t*)(smem + AKH + o) = hi;
            *(uint32_t*)(smem + AKL + o) = lo;
            hi = packsplit(vv.x, vv.y, lo);
            *(uint32_t*)(smem + AVH + o) = hi;
            *(uint32_t*)(smem + AVL + o) = lo;
        }
        if (tid < 64) ek_s[tid] = elev[b * SEQ + j0 + tid];
        __syncthreads();

        // ---- scores = split(Q) @ split(K)^T ----
        float sc[8][4] = {};
        #pragma unroll
        for (int kc = 0; kc < 4; kc++) {
            uint32_t aH4[4], aL4[4];
            uint32_t ao = asw(wm + rA, kc * 16 + cA);
            LDSM4(aH4, sb + AQH + ao);
            LDSM4(aL4, sb + AQL + ao);
            #pragma unroll
            for (int nt2 = 0; nt2 < 4; nt2++) {
                uint32_t bo = asw(nt2 * 16 + rB, kc * 16 + cB);
                uint32_t bh[4], bl[4];
                LDSM4(bh, sb + AKH + bo);
                LDSM4(bl, sb + AKL + bo);
                MMA16816(sc[2 * nt2],     aH4, bh);
                MMA16816(sc[2 * nt2],     aH4, bl);
                MMA16816(sc[2 * nt2],     aL4, bh);
                MMA16816(sc[2 * nt2 + 1], aH4, bh + 2);
                MMA16816(sc[2 * nt2 + 1], aH4, bl + 2);
                MMA16816(sc[2 * nt2 + 1], aL4, bh + 2);
            }
        }

        // ---- online softmax + elevation mask (registers only) ----
        float mx0 = -1e30f, mx1 = -1e30f;
        #pragma unroll
        for (int nt = 0; nt < 8; nt++) {
            mx0 = fmaxf(mx0, fmaxf(sc[nt][0], sc[nt][1]));
            mx1 = fmaxf(mx1, fmaxf(sc[nt][2], sc[nt][3]));
        }
        mx0 = fmaxf(mx0, __shfl_xor_sync(0xffffffffu, mx0, 1));
        mx0 = fmaxf(mx0, __shfl_xor_sync(0xffffffffu, mx0, 2));
        mx1 = fmaxf(mx1, __shfl_xor_sync(0xffffffffu, mx1, 1));
        mx1 = fmaxf(mx1, __shfl_xor_sync(0xffffffffu, mx1, 2));
        float mn0 = fmaxf(m0, mx0), mn1 = fmaxf(m1, mx1);
        float f0 = __expf(m0 - mn0), f1 = __expf(m1 - mn1);
        m0 = mn0; m1 = mn1;

        float eq0 = eq_s[wm + (lane >> 2)];
        float eq1 = eq_s[wm + (lane >> 2) + 8];
        float ps0 = 0.f, ps1 = 0.f, ss0 = 0.f, ss1 = 0.f;
        #pragma unroll
        for (int nt = 0; nt < 8; nt++) {
            int jc = nt * 8 + ((lane & 3) << 1);
            float ek0 = ek_s[jc], ek1 = ek_s[jc + 1];
            #pragma unroll
            for (int v = 0; v < 4; v++) {
                float mn = (v < 2) ? mn0 : mn1;
                float eq = (v < 2) ? eq0 : eq1;
                float ek = (v & 1) ? ek1 : ek0;
                float e = __expf(sc[nt][v] - mn);
                float msk = fmaxf(__fdividef(1.f, 1.f + __expf(bar * (ek - eq))), 1e-6f);
                float p = e * msk;
                sc[nt][v] = p;
                if (v < 2) { ps0 += p; ss0 += e; } else { ps1 += p; ss1 += e; }
            }
        }
        ps0 += __shfl_xor_sync(0xffffffffu, ps0, 1); ps0 += __shfl_xor_sync(0xffffffffu, ps0, 2);
        ps1 += __shfl_xor_sync(0xffffffffu, ps1, 1); ps1 += __shfl_xor_sync(0xffffffffu, ps1, 2);
        ss0 += __shfl_xor_sync(0xffffffffu, ss0, 1); ss0 += __shfl_xor_sync(0xffffffffu, ss0, 2);
        ss1 += __shfl_xor_sync(0xffffffffu, ss1, 1); ss1 += __shfl_xor_sync(0xffffffffu, ss1, 2);
        P0 = P0 * f0 + ps0; P1 = P1 * f1 + ps1;
        S0 = S0 * f0 + ss0; S1 = S1 * f1 + ss1;
        #pragma unroll
        for (int dt = 0; dt < 8; dt++) {
            oacc[dt][0] *= f0; oacc[dt][1] *= f0;
            oacc[dt][2] *= f1; oacc[dt][3] *= f1;
        }

        // ---- oacc += split(P) @ split(V) ----
        #pragma unroll
        for (int kc = 0; kc < 4; kc++) {
            uint32_t ph[4], pl[4];
            ph[0] = packsplit(sc[2 * kc][0],     sc[2 * kc][1],     pl[0]);
            ph[1] = packsplit(sc[2 * kc][2],     sc[2 * kc][3],     pl[1]);
            ph[2] = packsplit(sc[2 * kc + 1][0], sc[2 * kc + 1][1], pl[2]);
            ph[3] = packsplit(sc[2 * kc + 1][2], sc[2 * kc + 1][3], pl[3]);
            #pragma unroll
            for (int dt2 = 0; dt2 < 4; dt2++) {
                uint32_t vo = asw(kc * 16 + vj, dt2 * 16 + vd);
                uint32_t vh[4], vl[4];
                LDSM4T(vh, sb + AVH + vo);
                LDSM4T(vl, sb + AVL + vo);
                MMA16816(oacc[2 * dt2],     ph, vh);
                MMA16816(oacc[2 * dt2],     ph, vl);
                MMA16816(oacc[2 * dt2],     pl, vh);
                MMA16816(oacc[2 * dt2 + 1], ph, vh + 2);
                MMA16816(oacc[2 * dt2 + 1], ph, vl + 2);
                MMA16816(oacc[2 * dt2 + 1], pl, vh + 2);
            }
        }
    }

    // ---- writeout: normalize, split to bf16 hi/lo ----
    float inv0 = __fdividef(1.f, P0 + 1e-8f * S0);
    float inv1 = __fdividef(1.f, P1 + 1e-8f * S1);
    int r0 = b * SEQ + q0 + wm + (lane >> 2);
    int col = hoff + ((lane & 3) << 1);
    #pragma unroll
    for (int dt = 0; dt < 8; dt++) {
        uint32_t lo;
        uint32_t hi = packsplit(oacc[dt][0] * inv0, oacc[dt][1] * inv0, lo);
        size_t o = (size_t)r0 * DIMC + col + dt * 8;
        *(uint32_t*)(outH + o) = hi;
        *(uint32_t*)(outL + o) = lo;
        hi = packsplit(oacc[dt][2] * inv1, oacc[dt][3] * inv1, lo);
        o += (size_t)8 * DIMC;
        *(uint32_t*)(outH + o) = hi;
        *(uint32_t*)(outL + o) = lo;
    }
}

// ---------------- launch ----------------
extern "C" void kernel_launch(void* const* d_in, const int* in_sizes, int n_in,
                              void* d_out, int out_size) {
    const float* x       = (const float*)d_in[0];
    const float* elev    = (const float*)d_in[1];
    const float* qkv_w   = (const float*)d_in[2];
    const float* qkv_b   = (const float*)d_in[3];
    const float* proj_w  = (const float*)d_in[4];
    const float* proj_b  = (const float*)d_in[5];
    const float* ln1_g   = (const float*)d_in[6];
    const float* ln1_b   = (const float*)d_in[7];
    const float* ln2_g   = (const float*)d_in[8];
    const float* ln2_b   = (const float*)d_in[9];
    const float* fc1_w   = (const float*)d_in[10];
    const float* fc1_b   = (const float*)d_in[11];
    const float* fc2_w   = (const float*)d_in[12];
    const float* fc2_b   = (const float*)d_in[13];
    const float* barrier = (const float*)d_in[14];
    float* out = (float*)d_out;

    __nv_bfloat16 *aH, *aL, *fH, *fL;
    __nv_bfloat16 *wqH, *wqL, *wpH, *wpL, *w1H, *w1L, *w2H, *w2L;
    float* qkvb;
    cudaGetSymbolAddress((void**)&aH, g_aH);     cudaGetSymbolAddress((void**)&aL, g_aL);
    cudaGetSymbolAddress((void**)&fH, g_fH);     cudaGetSymbolAddress((void**)&fL, g_fL);
    cudaGetSymbolAddress((void**)&qkvb, g_qkv);
    cudaGetSymbolAddress((void**)&wqH, g_wqkvH); cudaGetSymbolAddress((void**)&wqL, g_wqkvL);
    cudaGetSymbolAddress((void**)&wpH, g_wprojH);cudaGetSymbolAddress((void**)&wpL, g_wprojL);
    cudaGetSymbolAddress((void**)&w1H, g_wfc1H); cudaGetSymbolAddress((void**)&w1L, g_wfc1L);
    cudaGetSymbolAddress((void**)&w2H, g_wfc2H); cudaGetSymbolAddress((void**)&w2L, g_wfc2L);

    const int GEMM_SMEM = 2 * STG;
    cudaFuncSetAttribute(gemm_mma<0>, cudaFuncAttributeMaxDynamicSharedMemorySize, GEMM_SMEM);
    cudaFuncSetAttribute(gemm_mma<1>, cudaFuncAttributeMaxDynamicSharedMemorySize, GEMM_SMEM);
    cudaFuncSetAttribute(gemm_mma<2>, cudaFuncAttributeMaxDynamicSharedMemorySize, GEMM_SMEM);
    cudaFuncSetAttribute(attn_mma, cudaFuncAttributeMaxDynamicSharedMemorySize, ATTN_SM);

    dim3 tb(32, 8);
    wsplit_t<<<dim3(3 * DIMC / 32, DIMC / 32), tb>>>(qkv_w, wqH, wqL, DIMC, 3 * DIMC);
    wsplit_t<<<dim3(DIMC / 32, DIMC / 32), tb>>>(proj_w, wpH, wpL, DIMC, DIMC);
    wsplit_t<<<dim3(HIDDENC / 32, DIMC / 32), tb>>>(fc1_w, w1H, w1L, DIMC, HIDDENC);
    wsplit_t<<<dim3(DIMC / 32, HIDDENC / 32), tb>>>(fc2_w, w2H, w2L, HIDDENC, DIMC);

    // 1. LN1 -> splits
    ln_split<<<ROWS, 256>>>(x, ln1_g, ln1_b, aH, aL);
    // 2. QKV = ln1 @ qkv_w + b
    gemm_mma<0><<<dim3(3 * DIMC / 128, ROWS / 128), 256, GEMM_SMEM>>>(
        aH, aL, wqH, wqL, qkv_b, nullptr, qkvb, nullptr, nullptr, ROWS, 3 * DIMC, DIMC);
    // 3. attention -> splits
    attn_mma<<<dim3(SEQ / 128, NHEADS, BATCH), 256, ATTN_SM>>>(qkvb, elev, barrier, aH, aL);
    // 4. x2 = x + attn @ proj_w + b -> d_out
    gemm_mma<1><<<dim3(DIMC / 128, ROWS / 128), 256, GEMM_SMEM>>>(
        aH, aL, wpH, wpL, proj_b, x, out, nullptr, nullptr, ROWS, DIMC, DIMC);
    // 5. LN2 -> splits
    ln_split<<<ROWS, 256>>>(out, ln2_g, ln2_b, aH, aL);
    // 6. fc1 + gelu -> splits
    gemm_mma<2><<<dim3(HIDDENC / 128, ROWS / 128), 256, GEMM_SMEM>>>(
        aH, aL, w1H, w1L, fc1_b, nullptr, nullptr, fH, fL, ROWS, HIDDENC, DIMC);
    // 7. out = x2 + fc1 @ fc2_w + b
    gemm_mma<1><<<dim3(DIMC / 128, ROWS / 128), 256, GEMM_SMEM>>>(
        fH, fL, w2H, w2L, fc2_b, out, out, nullptr, nullptr, ROWS, DIMC, HIDDENC);
}

// round 10
// speedup vs baseline: 2.2449x; 1.0151x over previous
#include <cuda_runtime.h>
#include <cuda_bf16.h>
#include <math.h>
#include <stdint.h>

#define DIMC 768
#define NHEADS 12
#define HD 64
#define HIDDENC 3072
#define SEQ 2048
#define BATCH 2
#define ROWS (BATCH * SEQ)   // 4096

// ---------------- scratch (device globals) ----------------
__device__ __nv_bfloat16 g_aH[ROWS * DIMC];
__device__ __nv_bfloat16 g_aL[ROWS * DIMC];
__device__ __nv_bfloat16 g_fH[ROWS * HIDDENC];
__device__ __nv_bfloat16 g_fL[ROWS * HIDDENC];
__device__ __nv_bfloat16 g_qkvH[ROWS * 3 * DIMC];
__device__ __nv_bfloat16 g_qkvL[ROWS * 3 * DIMC];
__device__ __nv_bfloat16 g_wqkvH[3 * DIMC * DIMC], g_wqkvL[3 * DIMC * DIMC];
__device__ __nv_bfloat16 g_wprojH[DIMC * DIMC],    g_wprojL[DIMC * DIMC];
__device__ __nv_bfloat16 g_wfc1H[HIDDENC * DIMC],  g_wfc1L[HIDDENC * DIMC];
__device__ __nv_bfloat16 g_wfc2H[DIMC * HIDDENC],  g_wfc2L[DIMC * HIDDENC];

// ---------------- helpers ----------------
__device__ __forceinline__ uint32_t smem_u32(const void* p) {
    uint32_t a;
    asm("{ .reg .u64 t; cvta.to.shared.u64 t, %1; cvt.u32.u64 %0, t; }" : "=r"(a) : "l"(p));
    return a;
}
__device__ __forceinline__ void cpa16(uint32_t dst, const void* src) {
    asm volatile("cp.async.cg.shared.global [%0], [%1], 16;" :: "r"(dst), "l"(src));
}
#define CP_COMMIT() asm volatile("cp.async.commit_group;" ::: "memory")
#define CP_WAIT(n)  asm volatile("cp.async.wait_group %0;" :: "n"(n) : "memory")

#define LDSM4(r, a) \
    asm volatile("ldmatrix.sync.aligned.m8n8.x4.shared.b16 {%0,%1,%2,%3}, [%4];" \
        : "=r"((r)[0]), "=r"((r)[1]), "=r"((r)[2]), "=r"((r)[3]) : "r"(a))
#define LDSM4T(r, a) \
    asm volatile("ldmatrix.sync.aligned.m8n8.x4.trans.shared.b16 {%0,%1,%2,%3}, [%4];" \
        : "=r"((r)[0]), "=r"((r)[1]), "=r"((r)[2]), "=r"((r)[3]) : "r"(a))

#define MMA16816(d, a, b) \
    asm volatile("mma.sync.aligned.m16n8k16.row.col.f32.bf16.bf16.f32 " \
        "{%0,%1,%2,%3}, {%4,%5,%6,%7}, {%8,%9}, {%0,%1,%2,%3};" \
        : "+f"((d)[0]), "+f"((d)[1]), "+f"((d)[2]), "+f"((d)[3]) \
        : "r"((a)[0]), "r"((a)[1]), "r"((a)[2]), "r"((a)[3]), "r"((b)[0]), "r"((b)[1]))

__device__ __forceinline__ void split2(float v, __nv_bfloat16& h, __nv_bfloat16& l) {
    h = __float2bfloat16(v);
    l = __float2bfloat16(v - __bfloat162float(h));
}
__device__ __forceinline__ uint32_t packsplit(float a, float b, uint32_t& lo) {
    __nv_bfloat16 ah, al, bh, bl;
    split2(a, ah, al);
    split2(b, bh, bl);
    lo = (uint32_t)__bfloat16_as_ushort(al) | ((uint32_t)__bfloat16_as_ushort(bl) << 16);
    return (uint32_t)__bfloat16_as_ushort(ah) | ((uint32_t)__bfloat16_as_ushort(bh) << 16);
}

// gemm tile swizzle: [128][32] bf16 packed in 64 x 128B rows
__device__ __forceinline__ uint32_t swz(int r, int c) {
    int p = r >> 1;
    int sub = ((r & 1) << 2) + (c >> 3);
    return (uint32_t)(p * 128 + (((sub ^ (p & 7)) << 4)) + ((c & 7) << 1));
}
// attention tile swizzle: [.][64] bf16, 128B per row (byte offset)
__device__ __forceinline__ uint32_t asw(int r, int c) {
    return (uint32_t)(r * 128 + ((((c >> 3) ^ (r & 7)) << 4)) + ((c & 7) << 1));
}

// ---------------- LayerNorm -> bf16 hi/lo split ----------------
__global__ void ln_split(const float* __restrict__ x,
                         const float* __restrict__ g,
                         const float* __restrict__ b,
                         __nv_bfloat16* __restrict__ oh,
                         __nv_bfloat16* __restrict__ ol) {
    int row = blockIdx.x;
    const float* xr = x + (size_t)row * DIMC;
    float s = 0.f, s2 = 0.f;
    for (int i = threadIdx.x; i < DIMC; i += 256) {
        float v = xr[i];
        s += v; s2 += v * v;
    }
    #pragma unroll
    for (int o = 16; o; o >>= 1) {
        s  += __shfl_xor_sync(0xffffffffu, s,  o);
        s2 += __shfl_xor_sync(0xffffffffu, s2, o);
    }
    __shared__ float sm[8], sq[8];
    __shared__ float mu_s, rs_s;
    int w = threadIdx.x >> 5, l = threadIdx.x & 31;
    if (l == 0) { sm[w] = s; sq[w] = s2; }
    __syncthreads();
    if (threadIdx.x == 0) {
        float S = 0.f, S2 = 0.f;
        #pragma unroll
        for (int i = 0; i < 8; i++) { S += sm[i]; S2 += sq[i]; }
        float mu = S / DIMC;
        float var = S2 / DIMC - mu * mu;
        mu_s = mu;
        rs_s = rsqrtf(var + 1e-5f);
    }
    __syncthreads();
    float mu = mu_s, rs = rs_s;
    for (int i = threadIdx.x; i < DIMC; i += 256) {
        float v = (xr[i] - mu) * rs * g[i] + b[i];
        __nv_bfloat16 h, lo;
        split2(v, h, lo);
        oh[(size_t)row * DIMC + i] = h;
        ol[(size_t)row * DIMC + i] = lo;
    }
}

// ---------------- weight transpose + split ----------------
__global__ void wsplit_t(const float* __restrict__ w,
                         __nv_bfloat16* __restrict__ oh,
                         __nv_bfloat16* __restrict__ ol, int K, int N) {
    __shared__ float t[32][33];
    int n0 = blockIdx.x * 32, k0 = blockIdx.y * 32;
    for (int r = threadIdx.y; r < 32; r += 8)
        t[r][threadIdx.x] = w[(size_t)(k0 + r) * N + n0 + threadIdx.x];
    __syncthreads();
    for (int r = threadIdx.y; r < 32; r += 8) {
        float v = t[threadIdx.x][r];
        __nv_bfloat16 h, lo;
        split2(v, h, lo);
        size_t o = (size_t)(n0 + r) * K + k0 + threadIdx.x;
        oh[o] = h;
        ol[o] = lo;
    }
}

// ---------------- HMMA GEMM, 3-stage pipeline ----------------
// EPI 1: C = acc + bias + res                (fp32)
// EPI 2: gelu(acc + bias) -> bf16 hi/lo (Ch/Cl)
// EPI 3: qkv: (acc+bias) * (col<DIMC ? 0.125 : 1) -> bf16 hi/lo (Ch/Cl)
#define STG 32768
#define GEMM_SMEM (3 * STG)
template <int EPI>
__global__ __launch_bounds__(256) void gemm_mma(
    const __nv_bfloat16* __restrict__ Ah, const __nv_bfloat16* __restrict__ Al,
    const __nv_bfloat16* __restrict__ Bh, const __nv_bfloat16* __restrict__ Bl,
    const float* __restrict__ bias, const float* __restrict__ res,
    float* __restrict__ C, __nv_bfloat16* __restrict__ Ch, __nv_bfloat16* __restrict__ Cl,
    int M, int N, int K) {
    extern __shared__ char smem[];
    uint32_t sb = smem_u32(smem);
    int tid = threadIdx.x, lane = tid & 31, w = tid >> 5;
    int m0 = blockIdx.y * 128, n0 = blockIdx.x * 128;
    int wm = (w & 3) * 32, wn = (w >> 2) * 64;

    float acc[2][8][4] = {};
    const int nchunk = K >> 5;

    int lr = tid >> 1;
    int ls0 = (tid & 1) * 2;
    uint32_t loff[2];
    #pragma unroll
    for (int j = 0; j < 2; j++) loff[j] = swz(lr, (ls0 + j) * 8);

    auto issue = [&](int c) {
        uint32_t st = sb + (uint32_t)(c % 3) * STG;
        int k0 = c << 5;
        #pragma unroll
        for (int j = 0; j < 2; j++) {
            size_t ga = (size_t)(m0 + lr) * K + k0 + (ls0 + j) * 8;
            size_t gb = (size_t)(n0 + lr) * K + k0 + (ls0 + j) * 8;
            cpa16(st + loff[j],         Ah + ga);
            cpa16(st + 8192 + loff[j],  Al + ga);
            cpa16(st + 16384 + loff[j], Bh + gb);
            cpa16(st + 24576 + loff[j], Bl + gb);
        }
        CP_COMMIT();
    };
    issue(0);
    if (nchunk > 1) issue(1);

    int rA = (lane & 15);
    int cAh = ((lane >> 4) << 3);
    int rB = (lane & 7) + ((lane >> 4) << 3);
    int cBh = (((lane >> 3) & 1) << 3);

    const uint32_t aoff[3] = {0u, 0u, 8192u};
    const uint32_t boff[3] = {16384u, 24576u, 16384u};

    for (int c = 0; c < nchunk; c++) {
        if (c + 2 < nchunk) issue(c + 2);
        int rem = nchunk - 1 - c;
        if (rem >= 2)      CP_WAIT(2);
        else if (rem == 1) CP_WAIT(1);
        else               CP_WAIT(0);
        __syncthreads();

        uint32_t stg = sb + (uint32_t)(c % 3) * STG;
        #pragma unroll
        for (int term = 0; term < 3; term++) {
            uint32_t Ab = stg + aoff[term];
            uint32_t Bb = stg + boff[term];
            #pragma unroll
            for (int ks = 0; ks < 32; ks += 16) {
                uint32_t afr[2][4];
                #pragma unroll
                for (int tm = 0; tm < 2; tm++)
                    LDSM4(afr[tm], Ab + swz(wm + tm * 16 + rA, ks + cAh));
                uint32_t bfr[8][2];
                #pragma unroll
                for (int t4 = 0; t4 < 4; t4++) {
                    uint32_t q[4];
                    LDSM4(q, Bb + swz(wn + t4 * 16 + rB, ks + cBh));
                    bfr[2 * t4][0] = q[0]; bfr[2 * t4][1] = q[1];
                    bfr[2 * t4 + 1][0] = q[2]; bfr[2 * t4 + 1][1] = q[3];
                }
                #pragma unroll
                for (int tm = 0; tm < 2; tm++)
                    #pragma unroll
                    for (int tn = 0; tn < 8; tn++)
                        MMA16816(acc[tm][tn], afr[tm], bfr[tn]);
            }
        }
        __syncthreads();
    }

    #pragma unroll
    for (int tm = 0; tm < 2; tm++) {
        #pragma unroll
        for (int tn = 0; tn < 8; tn++) {
            int row = m0 + wm + tm * 16 + (lane >> 2);
            int col = n0 + wn + tn * 8 + ((lane & 3) << 1);
            float b0 = bias[col], b1 = bias[col + 1];
            float* a = acc[tm][tn];
            #pragma unroll
            for (int hrow = 0; hrow < 2; hrow++) {
                int rr = row + hrow * 8;
                float v0 = a[2 * hrow + 0] + b0;
                float v1 = a[2 * hrow + 1] + b1;
                size_t o = (size_t)rr * N + col;
                if (EPI == 1) {
                    float2 rv = *(const float2*)(res + o);
                    float2 v = {v0 + rv.x, v1 + rv.y};
                    *(float2*)(C + o) = v;
                } else if (EPI == 2) {
                    float g0 = 0.5f * v0 * (1.0f + erff(v0 * 0.70710678118654752f));
                    float g1 = 0.5f * v1 * (1.0f + erff(v1 * 0.70710678118654752f));
                    uint32_t lo;
                    uint32_t hi = packsplit(g0, g1, lo);
                    *(uint32_t*)(Ch + o) = hi;
                    *(uint32_t*)(Cl + o) = lo;
                } else {
                    float scl = (col < DIMC) ? 0.125f : 1.0f;  // exact Q pre-scale
                    uint32_t lo;
                    uint32_t hi = packsplit(v0 * scl, v1 * scl, lo);
                    *(uint32_t*)(Ch + o) = hi;
                    *(uint32_t*)(Cl + o) = lo;
                }
            }
        }
    }
}

// ---------------- tensorized masked flash attention, cp.async staging ----------------
// Block: 128 q-rows x 1 head; 8 warps x 16 rows; j-tiles of 64, double-buffered.
// dyn smem: Qh 0 | Ql 16K | stage s at 32K + s*32K: {Kh, Kl, Vh, Vl} x 8KB
#define AQH 0
#define AQL 16384
#define ASTG0 32768
#define ATTN_SM 98304
__global__ __launch_bounds__(256) void attn_mma(
    const __nv_bfloat16* __restrict__ qkvH, const __nv_bfloat16* __restrict__ qkvL,
    const float* __restrict__ elev, const float* __restrict__ barrier_p,
    __nv_bfloat16* __restrict__ outH, __nv_bfloat16* __restrict__ outL) {
    extern __shared__ char smem[];
    uint32_t sb = smem_u32(smem);
    __shared__ float eq_s[128], ek_s[2][64];

    int tid = threadIdx.x, lane = tid & 31, w = tid >> 5;
    int q0 = blockIdx.x * 128;
    int h = blockIdx.y;
    int b = blockIdx.z;
    const float bar = barrier_p[0];
    const size_t base3 = (size_t)b * SEQ * (3 * DIMC);
    const int hoff = h * HD;
    const int wm = w * 16;

    // ---- stage Q via cp.async (pre-scaled, pre-split in gmem) ----
    // 2048 16B-chunks: arr(1b) | row(7b) | c8(3b)
    #pragma unroll
    for (int i = 0; i < 8; i++) {
        int ch = tid + 256 * i;
        int arr = ch >> 10, row = (ch >> 3) & 127, c8 = ch & 7;
        const __nv_bfloat16* src = (arr ? qkvL : qkvH) + base3 +
            (size_t)(q0 + row) * (3 * DIMC) + hoff + c8 * 8;
        cpa16(sb + (arr ? AQL : AQH) + asw(row, c8 * 8), src);
    }
    // ---- stage K/V tile 0 ----
    auto issueKV = [&](int jt) {
        uint32_t st = sb + ASTG0 + (uint32_t)(jt & 1) * 32768;
        int j0 = jt << 6;
        #pragma unroll
        for (int i = 0; i < 8; i++) {
            int ch = tid + 256 * i;
            int arr = ch >> 9, row = (ch >> 3) & 63, c8 = ch & 7;
            // arr: 0=Kh 1=Kl 2=Vh 3=Vl
            const __nv_bfloat16* bp = (arr & 1) ? qkvL : qkvH;
            int coff = (arr & 2) ? 2 * DIMC : DIMC;
            const __nv_bfloat16* src = bp + base3 +
                (size_t)(j0 + row) * (3 * DIMC) + coff + hoff + c8 * 8;
            cpa16(st + (uint32_t)arr * 8192 + asw(row, c8 * 8), src);
        }
        CP_COMMIT();
    };
    issueKV(0);
    if (tid < 128) eq_s[tid] = elev[b * SEQ + q0 + tid];
    if (tid < 64) ek_s[0][tid] = elev[b * SEQ + tid];

    float m0 = -1e30f, m1 = -1e30f;
    float P0 = 0.f, P1 = 0.f, S0 = 0.f, S1 = 0.f;
    float oacc[8][4] = {};

    const int rA = lane & 15;
    const int cA = (lane >> 4) << 3;
    const int rB = (lane & 7) + ((lane >> 4) << 3);
    const int cB = ((lane >> 3) & 1) << 3;
    const int vj = (((lane >> 3) & 1) << 3) + (lane & 7);
    const int vd = (lane >> 4) << 3;

    const int NJT = SEQ / 64;
    for (int jt = 0; jt < NJT; jt++) {
        if (jt + 1 < NJT) {
            issueKV(jt + 1);
            if (tid < 64) ek_s[(jt + 1) & 1][tid] = elev[b * SEQ + ((jt + 1) << 6) + tid];
            CP_WAIT(1);
        } else {
            CP_WAIT(0);
        }
        __syncthreads();
        uint32_t stg = sb + ASTG0 + (uint32_t)(jt & 1) * 32768;
        const float* eks = ek_s[jt & 1];

        // ---- scores = split(Q) @ split(K)^T ----
        float sc[8][4] = {};
        #pragma unroll
        for (int kc = 0; kc < 4; kc++) {
            uint32_t aH4[4], aL4[4];
            uint32_t ao = asw(wm + rA, kc * 16 + cA);
            LDSM4(aH4, sb + AQH + ao);
            LDSM4(aL4, sb + AQL + ao);
            #pragma unroll
            for (int nt2 = 0; nt2 < 4; nt2++) {
                uint32_t bo = asw(nt2 * 16 + rB, kc * 16 + cB);
                uint32_t bh[4], bl[4];
                LDSM4(bh, stg + bo);          // Kh
                LDSM4(bl, stg + 8192 + bo);   // Kl
                MMA16816(sc[2 * nt2],     aH4, bh);
                MMA16816(sc[2 * nt2],     aH4, bl);
                MMA16816(sc[2 * nt2],     aL4, bh);
                MMA16816(sc[2 * nt2 + 1], aH4, bh + 2);
                MMA16816(sc[2 * nt2 + 1], aH4, bl + 2);
                MMA16816(sc[2 * nt2 + 1], aL4, bh + 2);
            }
        }

        // ---- online softmax + elevation mask ----
        float mx0 = -1e30f, mx1 = -1e30f;
        #pragma unroll
        for (int nt = 0; nt < 8; nt++) {
            mx0 = fmaxf(mx0, fmaxf(sc[nt][0], sc[nt][1]));
            mx1 = fmaxf(mx1, fmaxf(sc[nt][2], sc[nt][3]));
        }
        mx0 = fmaxf(mx0, __shfl_xor_sync(0xffffffffu, mx0, 1));
        mx0 = fmaxf(mx0, __shfl_xor_sync(0xffffffffu, mx0, 2));
        mx1 = fmaxf(mx1, __shfl_xor_sync(0xffffffffu, mx1, 1));
        mx1 = fmaxf(mx1, __shfl_xor_sync(0xffffffffu, mx1, 2));
        float mn0 = fmaxf(m0, mx0), mn1 = fmaxf(m1, mx1);
        float f0 = __expf(m0 - mn0), f1 = __expf(m1 - mn1);
        m0 = mn0; m1 = mn1;

        float eq0 = eq_s[wm + (lane >> 2)];
        float eq1 = eq_s[wm + (lane >> 2) + 8];
        float ps0 = 0.f, ps1 = 0.f, ss0 = 0.f, ss1 = 0.f;
        #pragma unroll
        for (int nt = 0; nt < 8; nt++) {
            int jc = nt * 8 + ((lane & 3) << 1);
            float ek0 = eks[jc], ek1 = eks[jc + 1];
            #pragma unroll
            for (int v = 0; v < 4; v++) {
                float mn = (v < 2) ? mn0 : mn1;
                float eq = (v < 2) ? eq0 : eq1;
                float ek = (v & 1) ? ek1 : ek0;
                float e = __expf(sc[nt][v] - mn);
                float msk = fmaxf(__fdividef(1.f, 1.f + __expf(bar * (ek - eq))), 1e-6f);
                float p = e * msk;
                sc[nt][v] = p;
                if (v < 2) { ps0 += p; ss0 += e; } else { ps1 += p; ss1 += e; }
            }
        }
        ps0 += __shfl_xor_sync(0xffffffffu, ps0, 1); ps0 += __shfl_xor_sync(0xffffffffu, ps0, 2);
        ps1 += __shfl_xor_sync(0xffffffffu, ps1, 1); ps1 += __shfl_xor_sync(0xffffffffu, ps1, 2);
        ss0 += __shfl_xor_sync(0xffffffffu, ss0, 1); ss0 += __shfl_xor_sync(0xffffffffu, ss0, 2);
        ss1 += __shfl_xor_sync(0xffffffffu, ss1, 1); ss1 += __shfl_xor_sync(0xffffffffu, ss1, 2);
        P0 = P0 * f0 + ps0; P1 = P1 * f1 + ps1;
        S0 = S0 * f0 + ss0; S1 = S1 * f1 + ss1;
        #pragma unroll
        for (int dt = 0; dt < 8; dt++) {
            oacc[dt][0] *= f0; oacc[dt][1] *= f0;
            oacc[dt][2] *= f1; oacc[dt][3] *= f1;
        }

        // ---- oacc += split(P) @ split(V) ----
        #pragma unroll
        for (int kc = 0; kc < 4; kc++) {
            uint32_t ph[4], pl[4];
            ph[0] = packsplit(sc[2 * kc][0],     sc[2 * kc][1],     pl[0]);
            ph[1] = packsplit(sc[2 * kc][2],     sc[2 * kc][3],     pl[1]);
            ph[2] = packsplit(sc[2 * kc + 1][0], sc[2 * kc + 1][1], pl[2]);
            ph[3] = packsplit(sc[2 * kc + 1][2], sc[2 * kc + 1][3], pl[3]);
            #pragma unroll
            for (int dt2 = 0; dt2 < 4; dt2++) {
                uint32_t vo = asw(kc * 16 + vj, dt2 * 16 + vd);
                uint32_t vh[4], vl[4];
                LDSM4T(vh, stg + 16384 + vo);   // Vh
                LDSM4T(vl, stg + 24576 + vo);   // Vl
                MMA16816(oacc[2 * dt2],     ph, vh);
                MMA16816(oacc[2 * dt2],     ph, vl);
                MMA16816(oacc[2 * dt2],     pl, vh);
                MMA16816(oacc[2 * dt2 + 1], ph, vh + 2);
                MMA16816(oacc[2 * dt2 + 1], ph, vl + 2);
                MMA16816(oacc[2 * dt2 + 1], pl, vh + 2);
            }
        }
        __syncthreads();
    }

    // ---- writeout ----
    float inv0 = __fdividef(1.f, P0 + 1e-8f * S0);
    float inv1 = __fdividef(1.f, P1 + 1e-8f * S1);
    int r0 = b * SEQ + q0 + wm + (lane >> 2);
    int col = hoff + ((lane & 3) << 1);
    #pragma unroll
    for (int dt = 0; dt < 8; dt++) {
        uint32_t lo;
        uint32_t hi = packsplit(oacc[dt][0] * inv0, oacc[dt][1] * inv0, lo);
        size_t o = (size_t)r0 * DIMC + col + dt * 8;
        *(uint32_t*)(outH + o) = hi;
        *(uint32_t*)(outL + o) = lo;
        hi = packsplit(oacc[dt][2] * inv1, oacc[dt][3] * inv1, lo);
        o += (size_t)8 * DIMC;
        *(uint32_t*)(outH + o) = hi;
        *(uint32_t*)(outL + o) = lo;
    }
}

// ---------------- launch ----------------
extern "C" void kernel_launch(void* const* d_in, const int* in_sizes, int n_in,
                              void* d_out, int out_size) {
    const float* x       = (const float*)d_in[0];
    const float* elev    = (const float*)d_in[1];
    const float* qkv_w   = (const float*)d_in[2];
    const float* qkv_b   = (const float*)d_in[3];
    const float* proj_w  = (const float*)d_in[4];
    const float* proj_b  = (const float*)d_in[5];
    const float* ln1_g   = (const float*)d_in[6];
    const float* ln1_b   = (const float*)d_in[7];
    const float* ln2_g   = (const float*)d_in[8];
    const float* ln2_b   = (const float*)d_in[9];
    const float* fc1_w   = (const float*)d_in[10];
    const float* fc1_b   = (const float*)d_in[11];
    const float* fc2_w   = (const float*)d_in[12];
    const float* fc2_b   = (const float*)d_in[13];
    const float* barrier = (const float*)d_in[14];
    float* out = (float*)d_out;

    __nv_bfloat16 *aH, *aL, *fH, *fL, *qH, *qL;
    __nv_bfloat16 *wqH, *wqL, *wpH, *wpL, *w1H, *w1L, *w2H, *w2L;
    cudaGetSymbolAddress((void**)&aH, g_aH);     cudaGetSymbolAddress((void**)&aL, g_aL);
    cudaGetSymbolAddress((void**)&fH, g_fH);     cudaGetSymbolAddress((void**)&fL, g_fL);
    cudaGetSymbolAddress((void**)&qH, g_qkvH);   cudaGetSymbolAddress((void**)&qL, g_qkvL);
    cudaGetSymbolAddress((void**)&wqH, g_wqkvH); cudaGetSymbolAddress((void**)&wqL, g_wqkvL);
    cudaGetSymbolAddress((void**)&wpH, g_wprojH);cudaGetSymbolAddress((void**)&wpL, g_wprojL);
    cudaGetSymbolAddress((void**)&w1H, g_wfc1H); cudaGetSymbolAddress((void**)&w1L, g_wfc1L);
    cudaGetSymbolAddress((void**)&w2H, g_wfc2H); cudaGetSymbolAddress((void**)&w2L, g_wfc2L);

    cudaFuncSetAttribute(gemm_mma<1>, cudaFuncAttributeMaxDynamicSharedMemorySize, GEMM_SMEM);
    cudaFuncSetAttribute(gemm_mma<2>, cudaFuncAttributeMaxDynamicSharedMemorySize, GEMM_SMEM);
    cudaFuncSetAttribute(gemm_mma<3>, cudaFuncAttributeMaxDynamicSharedMemorySize, GEMM_SMEM);
    cudaFuncSetAttribute(attn_mma, cudaFuncAttributeMaxDynamicSharedMemorySize, ATTN_SM);

    dim3 tb(32, 8);
    wsplit_t<<<dim3(3 * DIMC / 32, DIMC / 32), tb>>>(qkv_w, wqH, wqL, DIMC, 3 * DIMC);
    wsplit_t<<<dim3(DIMC / 32, DIMC / 32), tb>>>(proj_w, wpH, wpL, DIMC, DIMC);
    wsplit_t<<<dim3(HIDDENC / 32, DIMC / 32), tb>>>(fc1_w, w1H, w1L, DIMC, HIDDENC);
    wsplit_t<<<dim3(DIMC / 32, HIDDENC / 32), tb>>>(fc2_w, w2H, w2L, HIDDENC, DIMC);

    // 1. LN1 -> splits
    ln_split<<<ROWS, 256>>>(x, ln1_g, ln1_b, aH, aL);
    // 2. QKV = ln1 @ qkv_w + b -> pre-split bf16 (Q scaled by 1/8)
    gemm_mma<3><<<dim3(3 * DIMC / 128, ROWS / 128), 256, GEMM_SMEM>>>(
        aH, aL, wqH, wqL, qkv_b, nullptr, nullptr, qH, qL, ROWS, 3 * DIMC, DIMC);
    // 3. attention -> splits
    attn_mma<<<dim3(SEQ / 128, NHEADS, BATCH), 256, ATTN_SM>>>(qH, qL, elev, barrier, aH, aL);
    // 4. x2 = x + attn @ proj_w + b -> d_out
    gemm_mma<1><<<dim3(DIMC / 128, ROWS / 128), 256, GEMM_SMEM>>>(
        aH, aL, wpH, wpL, proj_b, x, out, nullptr, nullptr, ROWS, DIMC, DIMC);
    // 5. LN2 -> splits
    ln_split<<<ROWS, 256>>>(out, ln2_g, ln2_b, aH, aL);
    // 6. fc1 + gelu -> splits
    gemm_mma<2><<<dim3(HIDDENC / 128, ROWS / 128), 256, GEMM_SMEM>>>(
        aH, aL, w1H, w1L, fc1_b, nullptr, nullptr, fH, fL, ROWS, HIDDENC, DIMC);
    // 7. out = x2 + fc1 @ fc2_w + b
    gemm_mma<1><<<dim3(DIMC / 128, ROWS / 128), 256, GEMM_SMEM>>>(
        fH, fL, w2H, w2L, fc2_b, out, out, nullptr, nullptr, ROWS, DIMC, HIDDENC);
}